// round 9
// baseline (speedup 1.0000x reference)
#include <cuda_runtime.h>
#include <cuda_fp16.h>
#include <stdint.h>

#define SEQ   4096
#define TTOK  16384
#define HID   2048
#define CINC  4096
#define COUTC 4096
#define GCH   512

#define BM 128
#define BN 128
#define BK 64
#define NST 3
#define NTHR 128
#define NCTA 296                              // 2 CTAs/SM * 148 SMs
#define STAGE_A (BM * BK * 2)                 // 16 KB
#define STAGE_BYTES (STAGE_A + BN * BK * 2)   // 32 KB
#define SMEM_TOTAL (NST * STAGE_BYTES)        // 96 KB -> 2 CTAs/SM

// fp16 copies of operands + intermediates (allocation-free rule: __device__ globals)
__device__ __half g_x16[(size_t)TTOK * HID];
__device__ __half g_h16[(size_t)TTOK * CINC];
__device__ __half g_y16[(size_t)TTOK * COUTC];
__device__ __half g_wi [(size_t)CINC * HID];
__device__ __half g_wo [(size_t)HID * COUTC];
__device__ __half g_w2 [(size_t)COUTC * 2048];

// One merged prep launch (4 regions)
#define P0 (TTOK * HID / 2)
#define P1 (P0 + CINC * HID / 2)
#define P2 (P1 + HID * COUTC / 2)
#define P3 (P2 + COUTC * 2048)
__global__ void prep_all_kernel(
    const float* __restrict__ x,  const float* __restrict__ wi_f,
    const float* __restrict__ wo_f, const float* __restrict__ cw,
    __half* __restrict__ x16, __half* __restrict__ wi,
    __half* __restrict__ wo,  __half* __restrict__ w2)
{
    int i = blockIdx.x * blockDim.x + threadIdx.x;
    if (i < P0) {
        float2 v = ((const float2*)x)[i];
        ((__half2*)x16)[i] = __floats2half2_rn(v.x, v.y);
    } else if (i < P1) {
        int j = i - P0;
        float2 v = ((const float2*)wi_f)[j];
        ((__half2*)wi)[j] = __floats2half2_rn(v.x, v.y);
    } else if (i < P2) {
        int j = i - P1;
        float2 v = ((const float2*)wo_f)[j];
        ((__half2*)wo)[j] = __floats2half2_rn(v.x, v.y);
    } else if (i < P3) {
        int j = i - P2;
        int co = j >> 11, r = j & 2047, tap = r >> 9, ci = r & 511;
        w2[j] = __float2half_rn(cw[(co * GCH + ci) * 4 + tap]);
    }
}

__device__ __forceinline__ uint32_t smem_u32(const void* p) {
    uint32_t a;
    asm("{ .reg .u64 t; cvta.to.shared.u64 t, %1; cvt.u32.u64 %0, t; }" : "=r"(a) : "l"(p));
    return a;
}

#define SW(x) ((x) ^ (((x) >> 3) & 0x70))

#define CPA(dst_, src_) \
    asm volatile("cp.async.cg.shared.global [%0], [%1], 16;" :: "r"(dst_), "l"(src_))
#define CPAZ(dst_, src_, sz_) \
    asm volatile("cp.async.cg.shared.global [%0], [%1], 16, %2;" :: "r"(dst_), "l"(src_), "r"(sz_))

#define LDSM4(r_, a_) \
    asm volatile("ldmatrix.sync.aligned.m8n8.x4.shared.b16 {%0,%1,%2,%3}, [%4];" \
        : "=r"((r_)[0]), "=r"((r_)[1]), "=r"((r_)[2]), "=r"((r_)[3]) : "r"(a_))

#define MMA16(c_, a_, b_) \
    asm volatile("mma.sync.aligned.m16n8k16.row.col.f32.f16.f16.f32 " \
        "{%0,%1,%2,%3},{%4,%5,%6,%7},{%8,%9},{%0,%1,%2,%3};" \
        : "+f"((c_)[0]), "+f"((c_)[1]), "+f"((c_)[2]), "+f"((c_)[3]) \
        : "r"((a_)[0]), "r"((a_)[1]), "r"((a_)[2]), "r"((a_)[3]), \
          "r"((b_)[0]), "r"((b_)[1]))

// Issue cp.async for pipeline step sp_ (tile = bid + (sp_/nK)*G, kt = sp_%nK)
// into stage sp_%NST. 128 thr: 8 A + 8 B chunks of 16B each.
#define ISSUE_STEP(sp_) do {                                                        \
    const int tile_ = bid + ((sp_) / nK) * G;                                       \
    const int kt_   = (sp_) % nK;                                                   \
    const int t0_   = (tile_ / NB) * BM;                                            \
    const int n0_   = (tile_ % NB) * BN;                                            \
    const int k0_   = kt_ * BK;                                                     \
    const uint32_t ab_ = sb + ((sp_) % NST) * STAGE_BYTES;                          \
    const uint32_t bb_ = ab_ + STAGE_A;                                             \
    if (!CONV) {                                                                    \
        _Pragma("unroll")                                                           \
        for (int j = 0; j < 8; j++) {                                               \
            int id_ = tid + j * NTHR, row_ = id_ >> 3, c_ = id_ & 7;                \
            const __half* s_p = A + (size_t)(t0_ + row_) * KVAL + k0_ + c_ * 8;     \
            CPA(ab_ + SW(row_ * 128 + c_ * 16), s_p);                               \
        }                                                                           \
    } else {                                                                        \
        const int tap_ = k0_ >> 9;                                                  \
        const int cb_  = (n0_ >> 9) * GCH + (k0_ & 511);                            \
        _Pragma("unroll")                                                           \
        for (int j = 0; j < 8; j++) {                                               \
            int id_ = tid + j * NTHR, row_ = id_ >> 3, c_ = id_ & 7;                \
            int tk_ = t0_ + row_;                                                   \
            uint32_t ok_ = (((tk_ & (SEQ - 1)) + tap_) >= 3) ? 16u : 0u;            \
            const __half* s_p = ok_                                                 \
                ? A + (size_t)(tk_ + tap_ - 3) * CINC + cb_ + c_ * 8 : A;           \
            CPAZ(ab_ + SW(row_ * 128 + c_ * 16), s_p, ok_);                         \
        }                                                                           \
    }                                                                               \
    _Pragma("unroll")                                                               \
    for (int j = 0; j < 8; j++) {                                                   \
        int id_ = tid + j * NTHR, row_ = id_ >> 3, c_ = id_ & 7;                    \
        const __half* s_p = Bw + (size_t)(n0_ + row_) * KVAL + k0_ + c_ * 8;        \
        CPA(bb_ + SW(row_ * 128 + c_ * 16), s_p);                                   \
    }                                                                               \
} while (0)

// Persistent-CTA GEMM: C[t,n] = act( sum_j A'[t,j]*Bw[n,j] + bias[n] ).
// 4 warps (2x2), warp tile 64x64, 2 CTAs/SM, continuous cross-tile cp.async
// pipeline: during the epilogue of tile T, stages for tile T+1 are in flight.
template<bool CONV, bool SILU, bool OUTF32, int KVAL, int NB, int NTILE>
__global__ void __launch_bounds__(NTHR, 2) gemm_p(
    const __half* __restrict__ A, const __half* __restrict__ Bw,
    const float* __restrict__ bias, void* __restrict__ Cp)
{
    constexpr int nK = KVAL / BK;
    constexpr int Nt = NB * BN;
    extern __shared__ char smem[];
    const uint32_t sb = smem_u32(smem);
    const int tid = threadIdx.x, lane = tid & 31, warp = tid >> 5;
    const int wm = (warp & 1) * 64, wn = (warp >> 1) * 64;
    const int bid = blockIdx.x, G = gridDim.x;

    const int nloc = (NTILE - bid + G - 1) / G;     // tiles owned by this CTA
    const int total_steps = nloc * nK;

    const int mtx  = lane >> 3;
    const int arow = (mtx & 1) * 8 + (lane & 7);
    const int acol = mtx >> 1;
    const int brow = (mtx >> 1) * 8 + (lane & 7);
    const int bcol = mtx & 1;

    // Prologue: first NST-1 steps
#pragma unroll
    for (int p = 0; p < NST - 1; p++) {
        if (p < total_steps) ISSUE_STEP(p);
        asm volatile("cp.async.commit_group;" ::: "memory");
    }

    int s = 0;
    for (int tl = 0; tl < nloc; tl++) {
        const int tile = bid + tl * G;
        const int t0 = (tile / NB) * BM, n0 = (tile % NB) * BN;

        float acc[4][8][4];
#pragma unroll
        for (int a = 0; a < 4; a++)
#pragma unroll
            for (int b = 0; b < 8; b++)
#pragma unroll
                for (int c = 0; c < 4; c++) acc[a][b][c] = 0.f;

        for (int kt = 0; kt < nK; kt++, s++) {
            asm volatile("cp.async.wait_group %0;" :: "n"(NST - 2) : "memory");
            __syncthreads();
            {
                const int sp = s + NST - 1;
                if (sp < total_steps) ISSUE_STEP(sp);
            }
            asm volatile("cp.async.commit_group;" ::: "memory");

            const uint32_t ab = sb + (s % NST) * STAGE_BYTES;
            const uint32_t bb = ab + STAGE_A;
#pragma unroll
            for (int ks = 0; ks < 4; ks++) {
                uint32_t af[4][4], bq[4][4];
#pragma unroll
                for (int mf = 0; mf < 4; mf++) {
                    int row = wm + mf * 16 + arow;
                    LDSM4(af[mf], ab + SW(row * 128 + (2 * ks + acol) * 16));
                }
#pragma unroll
                for (int pr = 0; pr < 4; pr++) {
                    int row = wn + pr * 16 + brow;
                    LDSM4(bq[pr], bb + SW(row * 128 + (2 * ks + bcol) * 16));
                }
#pragma unroll
                for (int mf = 0; mf < 4; mf++)
#pragma unroll
                    for (int nf = 0; nf < 8; nf++)
                        MMA16(acc[mf][nf], af[mf], &bq[nf >> 1][(nf & 1) * 2]);
            }
        }

        // Epilogue (next tile's first stages already in flight)
#pragma unroll
        for (int mf = 0; mf < 4; mf++) {
            int r = t0 + wm + mf * 16 + (lane >> 2);
#pragma unroll
            for (int nf = 0; nf < 8; nf++) {
                int cc = n0 + wn + nf * 8 + (lane & 3) * 2;
                float b0v = __ldg(bias + cc), b1v = __ldg(bias + cc + 1);
                float v0 = acc[mf][nf][0] + b0v;
                float v1 = acc[mf][nf][1] + b1v;
                float v2 = acc[mf][nf][2] + b0v;
                float v3 = acc[mf][nf][3] + b1v;
                if (SILU) {
                    v0 *= 1.f / (1.f + __expf(-v0));
                    v1 *= 1.f / (1.f + __expf(-v1));
                    v2 *= 1.f / (1.f + __expf(-v2));
                    v3 *= 1.f / (1.f + __expf(-v3));
                }
                if (OUTF32) {
                    float* C = (float*)Cp;
                    *(float2*)(C + (size_t)r * Nt + cc)       = make_float2(v0, v1);
                    *(float2*)(C + (size_t)(r + 8) * Nt + cc) = make_float2(v2, v3);
                } else {
                    __half2* C = (__half2*)Cp;
                    C[((size_t)r * Nt + cc) >> 1]       = __floats2half2_rn(v0, v1);
                    C[((size_t)(r + 8) * Nt + cc) >> 1] = __floats2half2_rn(v2, v3);
                }
            }
        }
    }
}

extern "C" void kernel_launch(void* const* d_in, const int* in_sizes, int n_in,
                              void* d_out, int out_size)
{
    const float* x      = (const float*)d_in[0];
    const float* W_in   = (const float*)d_in[1];
    const float* b_in   = (const float*)d_in[2];
    const float* conv_w = (const float*)d_in[3];
    const float* conv_b = (const float*)d_in[4];
    const float* W_out  = (const float*)d_in[5];
    const float* b_out  = (const float*)d_in[6];
    float* out = (float*)d_out;

    __half *x16, *h16, *y16, *wi, *wo, *w2;
    cudaGetSymbolAddress((void**)&x16, g_x16);
    cudaGetSymbolAddress((void**)&h16, g_h16);
    cudaGetSymbolAddress((void**)&y16, g_y16);
    cudaGetSymbolAddress((void**)&wi,  g_wi);
    cudaGetSymbolAddress((void**)&wo,  g_wo);
    cudaGetSymbolAddress((void**)&w2,  g_w2);

    cudaFuncSetAttribute((gemm_p<false, false, false, 2048, 32, 4096>),
                         cudaFuncAttributeMaxDynamicSharedMemorySize, SMEM_TOTAL);
    cudaFuncSetAttribute((gemm_p<true, true, false, 2048, 32, 4096>),
                         cudaFuncAttributeMaxDynamicSharedMemorySize, SMEM_TOTAL);
    cudaFuncSetAttribute((gemm_p<false, false, true, 4096, 16, 2048>),
                         cudaFuncAttributeMaxDynamicSharedMemorySize, SMEM_TOTAL);

    prep_all_kernel<<<(P3 + 255) / 256, 256>>>(x, W_in, W_out, conv_w,
                                               x16, wi, wo, w2);

    // Stage 1: h = x @ W_in^T + b_in               (K=2048, N=4096) -> fp16
    gemm_p<false, false, false, 2048, 32, 4096><<<NCTA, NTHR, SMEM_TOTAL>>>(
        x16, wi, b_in, h16);
    // Stage 2: y = silu(im2col(h) @ w2^T + conv_b) (K=2048, N=4096) -> fp16
    gemm_p<true, true, false, 2048, 32, 4096><<<NCTA, NTHR, SMEM_TOTAL>>>(
        h16, w2, conv_b, y16);
    // Stage 3: out = y @ W_out^T + b_out           (K=4096, N=2048) -> fp32
    gemm_p<false, false, true, 4096, 16, 2048><<<NCTA, NTHR, SMEM_TOTAL>>>(
        y16, wo, b_out, out);
}

// round 10
// speedup vs baseline: 1.0458x; 1.0458x over previous
#include <cuda_runtime.h>
#include <cuda_fp16.h>
#include <stdint.h>

#define SEQ   4096
#define TTOK  16384
#define HID   2048
#define CINC  4096
#define COUTC 4096
#define GCH   512

#define BM 128
#define BN 128
#define BK 64
#define NST 3
#define NTHR 128
#define NCTA 296                              // 2 CTAs/SM * 148 SMs
#define STAGE_A (BM * BK * 2)                 // 16 KB
#define STAGE_BYTES (STAGE_A + BN * BK * 2)   // 32 KB
#define SMEM_TOTAL (NST * STAGE_BYTES)        // 96 KB -> 2 CTAs/SM

// fp16 copies of operands + intermediates (allocation-free rule: __device__ globals)
__device__ __half g_x16[(size_t)TTOK * HID];
__device__ __half g_h16[(size_t)TTOK * CINC];
__device__ __half g_y16[(size_t)TTOK * COUTC];
__device__ __half g_wi [(size_t)CINC * HID];
__device__ __half g_wo [(size_t)HID * COUTC];
__device__ __half g_w2 [(size_t)COUTC * 2048];

// One merged prep launch (4 regions)
#define P0 (TTOK * HID / 2)
#define P1 (P0 + CINC * HID / 2)
#define P2 (P1 + HID * COUTC / 2)
#define P3 (P2 + COUTC * 2048)
__global__ void prep_all_kernel(
    const float* __restrict__ x,  const float* __restrict__ wi_f,
    const float* __restrict__ wo_f, const float* __restrict__ cw,
    __half* __restrict__ x16, __half* __restrict__ wi,
    __half* __restrict__ wo,  __half* __restrict__ w2)
{
    int i = blockIdx.x * blockDim.x + threadIdx.x;
    if (i < P0) {
        float2 v = ((const float2*)x)[i];
        ((__half2*)x16)[i] = __floats2half2_rn(v.x, v.y);
    } else if (i < P1) {
        int j = i - P0;
        float2 v = ((const float2*)wi_f)[j];
        ((__half2*)wi)[j] = __floats2half2_rn(v.x, v.y);
    } else if (i < P2) {
        int j = i - P1;
        float2 v = ((const float2*)wo_f)[j];
        ((__half2*)wo)[j] = __floats2half2_rn(v.x, v.y);
    } else if (i < P3) {
        int j = i - P2;
        int co = j >> 11, r = j & 2047, tap = r >> 9, ci = r & 511;
        w2[j] = __float2half_rn(cw[(co * GCH + ci) * 4 + tap]);
    }
}

__device__ __forceinline__ uint32_t smem_u32(const void* p) {
    uint32_t a;
    asm("{ .reg .u64 t; cvta.to.shared.u64 t, %1; cvt.u32.u64 %0, t; }" : "=r"(a) : "l"(p));
    return a;
}

#define SW(x) ((x) ^ (((x) >> 3) & 0x70))

#define CPA(dst_, src_) \
    asm volatile("cp.async.cg.shared.global [%0], [%1], 16;" :: "r"(dst_), "l"(src_))
#define CPAZ(dst_, src_, sz_) \
    asm volatile("cp.async.cg.shared.global [%0], [%1], 16, %2;" :: "r"(dst_), "l"(src_), "r"(sz_))

#define LDSM4(r_, a_) \
    asm volatile("ldmatrix.sync.aligned.m8n8.x4.shared.b16 {%0,%1,%2,%3}, [%4];" \
        : "=r"((r_)[0]), "=r"((r_)[1]), "=r"((r_)[2]), "=r"((r_)[3]) : "r"(a_))

#define MMA16(c_, a_, b_) \
    asm volatile("mma.sync.aligned.m16n8k16.row.col.f32.f16.f16.f32 " \
        "{%0,%1,%2,%3},{%4,%5,%6,%7},{%8,%9},{%0,%1,%2,%3};" \
        : "+f"((c_)[0]), "+f"((c_)[1]), "+f"((c_)[2]), "+f"((c_)[3]) \
        : "r"((a_)[0]), "r"((a_)[1]), "r"((a_)[2]), "r"((a_)[3]), \
          "r"((b_)[0]), "r"((b_)[1]))

// Load all af/bq fragments for one ks group from stage bases ab_/bb_ (in-place).
#define LOAD_FRAGS(ab_, bb_, ks_) do {                                              \
    _Pragma("unroll")                                                               \
    for (int mf_ = 0; mf_ < 4; mf_++) {                                             \
        int row_ = wm + mf_ * 16 + arow;                                            \
        LDSM4(af[mf_], (ab_) + SW(row_ * 128 + (2 * (ks_) + acol) * 16));           \
    }                                                                               \
    _Pragma("unroll")                                                               \
    for (int pr_ = 0; pr_ < 4; pr_++) {                                             \
        int row_ = wn + pr_ * 16 + brow;                                            \
        LDSM4(bq[pr_], (bb_) + SW(row_ * 128 + (2 * (ks_) + bcol) * 16));           \
    }                                                                               \
} while (0)

// Issue cp.async for pipeline step sp_ (tile = bid + (sp_/nK)*G, kt = sp_%nK)
// into stage sp_%NST. 128 thr: 8 A + 8 B chunks of 16B each.
#define ISSUE_STEP(sp_) do {                                                        \
    const int tile_ = bid + ((sp_) / nK) * G;                                       \
    const int kt_   = (sp_) % nK;                                                   \
    const int t0_   = (tile_ / NB) * BM;                                            \
    const int n0_   = (tile_ % NB) * BN;                                            \
    const int k0_   = kt_ * BK;                                                     \
    const uint32_t ab_ = sb + ((sp_) % NST) * STAGE_BYTES;                          \
    const uint32_t bb_ = ab_ + STAGE_A;                                             \
    if (!CONV) {                                                                    \
        _Pragma("unroll")                                                           \
        for (int j = 0; j < 8; j++) {                                               \
            int id_ = tid + j * NTHR, row_ = id_ >> 3, c_ = id_ & 7;                \
            const __half* s_p = A + (size_t)(t0_ + row_) * KVAL + k0_ + c_ * 8;     \
            CPA(ab_ + SW(row_ * 128 + c_ * 16), s_p);                               \
        }                                                                           \
    } else {                                                                        \
        const int tap_ = k0_ >> 9;                                                  \
        const int cb_  = (n0_ >> 9) * GCH + (k0_ & 511);                            \
        _Pragma("unroll")                                                           \
        for (int j = 0; j < 8; j++) {                                               \
            int id_ = tid + j * NTHR, row_ = id_ >> 3, c_ = id_ & 7;                \
            int tk_ = t0_ + row_;                                                   \
            uint32_t ok_ = (((tk_ & (SEQ - 1)) + tap_) >= 3) ? 16u : 0u;            \
            const __half* s_p = ok_                                                 \
                ? A + (size_t)(tk_ + tap_ - 3) * CINC + cb_ + c_ * 8 : A;           \
            CPAZ(ab_ + SW(row_ * 128 + c_ * 16), s_p, ok_);                         \
        }                                                                           \
    }                                                                               \
    _Pragma("unroll")                                                               \
    for (int j = 0; j < 8; j++) {                                                   \
        int id_ = tid + j * NTHR, row_ = id_ >> 3, c_ = id_ & 7;                    \
        const __half* s_p = Bw + (size_t)(n0_ + row_) * KVAL + k0_ + c_ * 8;        \
        CPA(bb_ + SW(row_ * 128 + c_ * 16), s_p);                                   \
    }                                                                               \
} while (0)

// Persistent-CTA GEMM with cross-barrier fragment pipelining:
// frags for (step s+1, ks=0) are LDSM'd in-place during step s's last MMA
// block (data validity guaranteed by the wait_group 0 at end of step s-1),
// so the tensor pipe never waits on a post-barrier LDS refill.
template<bool CONV, bool SILU, bool OUTF32, int KVAL, int NB, int NTILE>
__global__ void __launch_bounds__(NTHR, 2) gemm_p(
    const __half* __restrict__ A, const __half* __restrict__ Bw,
    const float* __restrict__ bias, void* __restrict__ Cp)
{
    constexpr int nK = KVAL / BK;
    constexpr int Nt = NB * BN;
    extern __shared__ char smem[];
    const uint32_t sb = smem_u32(smem);
    const int tid = threadIdx.x, lane = tid & 31, warp = tid >> 5;
    const int wm = (warp & 1) * 64, wn = (warp >> 1) * 64;
    const int bid = blockIdx.x, G = gridDim.x;

    const int nloc = (NTILE - bid + G - 1) / G;     // tiles owned by this CTA
    const int total_steps = nloc * nK;

    const int mtx  = lane >> 3;
    const int arow = (mtx & 1) * 8 + (lane & 7);
    const int acol = mtx >> 1;
    const int brow = (mtx >> 1) * 8 + (lane & 7);
    const int bcol = mtx & 1;

    uint32_t af[4][4], bq[4][4];                    // persistent frag registers

    // Prologue: issue steps 0..NST-2, land them, preload frags (step0, ks0)
#pragma unroll
    for (int p = 0; p < NST - 1; p++) {
        if (p < total_steps) ISSUE_STEP(p);
        asm volatile("cp.async.commit_group;" ::: "memory");
    }
    asm volatile("cp.async.wait_group 0;" ::: "memory");
    __syncthreads();
    LOAD_FRAGS(sb, sb + STAGE_A, 0);

    int s = 0;
    for (int tl = 0; tl < nloc; tl++) {
        const int tile = bid + tl * G;
        const int t0 = (tile / NB) * BM, n0 = (tile % NB) * BN;

        float acc[4][8][4];
#pragma unroll
        for (int a = 0; a < 4; a++)
#pragma unroll
            for (int b = 0; b < 8; b++)
#pragma unroll
                for (int c = 0; c < 4; c++) acc[a][b][c] = 0.f;

        for (int kt = 0; kt < nK; kt++, s++) {
            {
                const int sp = s + NST - 1;
                if (sp < total_steps) ISSUE_STEP(sp);
            }
            asm volatile("cp.async.commit_group;" ::: "memory");

            const uint32_t ab  = sb + (s % NST) * STAGE_BYTES;
            const uint32_t bb  = ab + STAGE_A;
            const uint32_t abn = sb + ((s + 1) % NST) * STAGE_BYTES;
            const uint32_t bbn = abn + STAGE_A;
#pragma unroll
            for (int ks = 0; ks < 4; ks++) {
                // MMAs consume the frags loaded one ks earlier
#pragma unroll
                for (int mf = 0; mf < 4; mf++)
#pragma unroll
                    for (int nf = 0; nf < 8; nf++)
                        MMA16(acc[mf][nf], af[mf], &bq[nf >> 1][(nf & 1) * 2]);
                // In-place prefetch of the next frag group (WAR via scoreboard).
                // ks==3 reads stage s+1: its data landed (wait_group 0 at the
                // end of step s-1 covered that group).
                if (ks < 3) LOAD_FRAGS(ab, bb, ks + 1);
                else        LOAD_FRAGS(abn, bbn, 0);
            }

            asm volatile("cp.async.wait_group 0;" ::: "memory");
            __syncthreads();
        }

        // Epilogue (frags for the next tile's first step already in registers;
        // next step's cp.async stages in flight)
#pragma unroll
        for (int mf = 0; mf < 4; mf++) {
            int r = t0 + wm + mf * 16 + (lane >> 2);
#pragma unroll
            for (int nf = 0; nf < 8; nf++) {
                int cc = n0 + wn + nf * 8 + (lane & 3) * 2;
                float b0v = __ldg(bias + cc), b1v = __ldg(bias + cc + 1);
                float v0 = acc[mf][nf][0] + b0v;
                float v1 = acc[mf][nf][1] + b1v;
                float v2 = acc[mf][nf][2] + b0v;
                float v3 = acc[mf][nf][3] + b1v;
                if (SILU) {
                    v0 *= 1.f / (1.f + __expf(-v0));
                    v1 *= 1.f / (1.f + __expf(-v1));
                    v2 *= 1.f / (1.f + __expf(-v2));
                    v3 *= 1.f / (1.f + __expf(-v3));
                }
                if (OUTF32) {
                    float* C = (float*)Cp;
                    *(float2*)(C + (size_t)r * Nt + cc)       = make_float2(v0, v1);
                    *(float2*)(C + (size_t)(r + 8) * Nt + cc) = make_float2(v2, v3);
                } else {
                    __half2* C = (__half2*)Cp;
                    C[((size_t)r * Nt + cc) >> 1]       = __floats2half2_rn(v0, v1);
                    C[((size_t)(r + 8) * Nt + cc) >> 1] = __floats2half2_rn(v2, v3);
                }
            }
        }
    }
}

extern "C" void kernel_launch(void* const* d_in, const int* in_sizes, int n_in,
                              void* d_out, int out_size)
{
    const float* x      = (const float*)d_in[0];
    const float* W_in   = (const float*)d_in[1];
    const float* b_in   = (const float*)d_in[2];
    const float* conv_w = (const float*)d_in[3];
    const float* conv_b = (const float*)d_in[4];
    const float* W_out  = (const float*)d_in[5];
    const float* b_out  = (const float*)d_in[6];
    float* out = (float*)d_out;

    __half *x16, *h16, *y16, *wi, *wo, *w2;
    cudaGetSymbolAddress((void**)&x16, g_x16);
    cudaGetSymbolAddress((void**)&h16, g_h16);
    cudaGetSymbolAddress((void**)&y16, g_y16);
    cudaGetSymbolAddress((void**)&wi,  g_wi);
    cudaGetSymbolAddress((void**)&wo,  g_wo);
    cudaGetSymbolAddress((void**)&w2,  g_w2);

    cudaFuncSetAttribute((gemm_p<false, false, false, 2048, 32, 4096>),
                         cudaFuncAttributeMaxDynamicSharedMemorySize, SMEM_TOTAL);
    cudaFuncSetAttribute((gemm_p<true, true, false, 2048, 32, 4096>),
                         cudaFuncAttributeMaxDynamicSharedMemorySize, SMEM_TOTAL);
    cudaFuncSetAttribute((gemm_p<false, false, true, 4096, 16, 2048>),
                         cudaFuncAttributeMaxDynamicSharedMemorySize, SMEM_TOTAL);

    prep_all_kernel<<<(P3 + 255) / 256, 256>>>(x, W_in, W_out, conv_w,
                                               x16, wi, wo, w2);

    // Stage 1: h = x @ W_in^T + b_in               (K=2048, N=4096) -> fp16
    gemm_p<false, false, false, 2048, 32, 4096><<<NCTA, NTHR, SMEM_TOTAL>>>(
        x16, wi, b_in, h16);
    // Stage 2: y = silu(im2col(h) @ w2^T + conv_b) (K=2048, N=4096) -> fp16
    gemm_p<true, true, false, 2048, 32, 4096><<<NCTA, NTHR, SMEM_TOTAL>>>(
        h16, w2, conv_b, y16);
    // Stage 3: out = y @ W_out^T + b_out           (K=4096, N=2048) -> fp32
    gemm_p<false, false, true, 4096, 16, 2048><<<NCTA, NTHR, SMEM_TOTAL>>>(
        y16, wo, b_out, out);
}

// round 11
// speedup vs baseline: 1.2016x; 1.1490x over previous
#include <cuda_runtime.h>
#include <cuda_fp16.h>
#include <stdint.h>

#define SEQ   4096
#define TTOK  16384
#define HID   2048
#define CINC  4096
#define COUTC 4096
#define GCH   512

#define BM 128
#define BN 128
#define BK 64
#define NST 3
#define NTHR 128
#define NCTA 296                              // 2 CTAs/SM * 148 SMs
#define STAGE_A (BM * BK * 2)                 // 16 KB
#define STAGE_BYTES (STAGE_A + BN * BK * 2)   // 32 KB
#define SMEM_TOTAL (NST * STAGE_BYTES)        // 96 KB -> 2 CTAs/SM

// fp16 copies of operands + intermediates (allocation-free rule: __device__ globals)
__device__ __half g_x16[(size_t)TTOK * HID];
__device__ __half g_h16[(size_t)TTOK * CINC];
__device__ __half g_y16[(size_t)TTOK * COUTC];
__device__ __half g_wi [(size_t)CINC * HID];
__device__ __half g_wo [(size_t)HID * COUTC];
__device__ __half g_w2 [(size_t)COUTC * 2048];

// One merged prep launch (4 regions)
#define P0 (TTOK * HID / 2)
#define P1 (P0 + CINC * HID / 2)
#define P2 (P1 + HID * COUTC / 2)
#define P3 (P2 + COUTC * 2048)
__global__ void prep_all_kernel(
    const float* __restrict__ x,  const float* __restrict__ wi_f,
    const float* __restrict__ wo_f, const float* __restrict__ cw,
    __half* __restrict__ x16, __half* __restrict__ wi,
    __half* __restrict__ wo,  __half* __restrict__ w2)
{
    int i = blockIdx.x * blockDim.x + threadIdx.x;
    if (i < P0) {
        float2 v = ((const float2*)x)[i];
        ((__half2*)x16)[i] = __floats2half2_rn(v.x, v.y);
    } else if (i < P1) {
        int j = i - P0;
        float2 v = ((const float2*)wi_f)[j];
        ((__half2*)wi)[j] = __floats2half2_rn(v.x, v.y);
    } else if (i < P2) {
        int j = i - P1;
        float2 v = ((const float2*)wo_f)[j];
        ((__half2*)wo)[j] = __floats2half2_rn(v.x, v.y);
    } else if (i < P3) {
        int j = i - P2;
        int co = j >> 11, r = j & 2047, tap = r >> 9, ci = r & 511;
        w2[j] = __float2half_rn(cw[(co * GCH + ci) * 4 + tap]);
    }
}

__device__ __forceinline__ uint32_t smem_u32(const void* p) {
    uint32_t a;
    asm("{ .reg .u64 t; cvta.to.shared.u64 t, %1; cvt.u32.u64 %0, t; }" : "=r"(a) : "l"(p));
    return a;
}

#define SW(x) ((x) ^ (((x) >> 3) & 0x70))

#define CPA(dst_, src_) \
    asm volatile("cp.async.cg.shared.global [%0], [%1], 16;" :: "r"(dst_), "l"(src_))
#define CPAZ(dst_, src_, sz_) \
    asm volatile("cp.async.cg.shared.global [%0], [%1], 16, %2;" :: "r"(dst_), "l"(src_), "r"(sz_))

#define LDSM4(r_, a_) \
    asm volatile("ldmatrix.sync.aligned.m8n8.x4.shared.b16 {%0,%1,%2,%3}, [%4];" \
        : "=r"((r_)[0]), "=r"((r_)[1]), "=r"((r_)[2]), "=r"((r_)[3]) : "r"(a_))

#define MMA16(c_, a_, b_) \
    asm volatile("mma.sync.aligned.m16n8k16.row.col.f32.f16.f16.f32 " \
        "{%0,%1,%2,%3},{%4,%5,%6,%7},{%8,%9},{%0,%1,%2,%3};" \
        : "+f"((c_)[0]), "+f"((c_)[1]), "+f"((c_)[2]), "+f"((c_)[3]) \
        : "r"((a_)[0]), "r"((a_)[1]), "r"((a_)[2]), "r"((a_)[3]), \
          "r"((b_)[0]), "r"((b_)[1]))

// Load all af/bq fragments for one ks group from stage bases ab_/bb_ (in-place).
#define LOAD_FRAGS(ab_, bb_, ks_) do {                                              \
    _Pragma("unroll")                                                               \
    for (int mf_ = 0; mf_ < 4; mf_++) {                                             \
        int row_ = wm + mf_ * 16 + arow;                                            \
        LDSM4(af[mf_], (ab_) + SW(row_ * 128 + (2 * (ks_) + acol) * 16));           \
    }                                                                               \
    _Pragma("unroll")                                                               \
    for (int pr_ = 0; pr_ < 4; pr_++) {                                             \
        int row_ = wn + pr_ * 16 + brow;                                            \
        LDSM4(bq[pr_], (bb_) + SW(row_ * 128 + (2 * (ks_) + bcol) * 16));           \
    }                                                                               \
} while (0)

// Full-step issue (prologue only). 128 thr: 8 A + 8 B chunks of 16B.
#define ISSUE_STEP(sp_) do {                                                        \
    const int tile_ = bid + ((sp_) / nK) * G;                                       \
    const int kt_   = (sp_) % nK;                                                   \
    const int t0_   = (tile_ / NB) * BM;                                            \
    const int n0_   = (tile_ % NB) * BN;                                            \
    const int k0_   = kt_ * BK;                                                     \
    const uint32_t ab_ = sb + ((sp_) % NST) * STAGE_BYTES;                          \
    const uint32_t bb_ = ab_ + STAGE_A;                                             \
    if (!CONV) {                                                                    \
        _Pragma("unroll")                                                           \
        for (int j = 0; j < 8; j++) {                                               \
            const __half* s_p = A + (size_t)(t0_ + lr + 16 * j) * KVAL + k0_ + lc * 8; \
            CPA(ab_ + SW(lr * 128 + lc * 16) + j * 2048, s_p);                      \
        }                                                                           \
    } else {                                                                        \
        const int tap_ = k0_ >> 9;                                                  \
        const int pb_  = (t0_ & (SEQ - 1)) + lr + tap_;                             \
        const __half* cbase_ = A + (size_t)(t0_ + lr + tap_ - 3) * CINC             \
                             + (n0_ >> 9) * GCH + (k0_ & 511) + lc * 8;             \
        _Pragma("unroll")                                                           \
        for (int j = 0; j < 8; j++) {                                               \
            uint32_t ok_ = (pb_ + 16 * j >= 3) ? 16u : 0u;                          \
            const __half* s_p = ok_ ? cbase_ + (size_t)(16 * j) * CINC : A;         \
            CPAZ(ab_ + SW(lr * 128 + lc * 16) + j * 2048, s_p, ok_);                \
        }                                                                           \
    }                                                                               \
    _Pragma("unroll")                                                               \
    for (int j = 0; j < 8; j++) {                                                   \
        const __half* s_p = Bw + (size_t)(n0_ + lr + 16 * j) * KVAL + k0_ + lc * 8; \
        CPA(bb_ + SW(lr * 128 + lc * 16) + j * 2048, s_p);                          \
    }                                                                               \
} while (0)

// Quarter issue: chunks 2q, 2q+1 of A and B from per-step precomputed bases.
// Swizzle-linearity: +16 rows = +2048 bytes, swizzle bits [7:9] unchanged.
#define ISSUE_QTR(q_) do {                                                          \
    if (doiss) {                                                                    \
        _Pragma("unroll")                                                           \
        for (int j = 2 * (q_); j < 2 * (q_) + 2; j++) {                             \
            if (!CONV) {                                                            \
                CPA(dstA + j * 2048, srcA + (size_t)(16 * j) * KVAL);               \
            } else {                                                                \
                uint32_t ok_ = (pbase + 16 * j >= 3) ? 16u : 0u;                    \
                const __half* s_p = ok_ ? srcC + (size_t)(16 * j) * CINC : A;       \
                CPAZ(dstA + j * 2048, s_p, ok_);                                    \
            }                                                                       \
            CPA(dstB + j * 2048, srcB + (size_t)(16 * j) * KVAL);                   \
        }                                                                           \
    }                                                                               \
} while (0)

// Persistent-CTA GEMM. Cross-barrier frag pipelining + cp.async issue spread
// across the 4 ks MMA blocks (wait_group 1 never waits on the group issued in
// the current step; ks0 frags load post-barrier from the guaranteed stage).
template<bool CONV, bool SILU, bool OUTF32, int KVAL, int NB, int NTILE>
__global__ void __launch_bounds__(NTHR, 2) gemm_p(
    const __half* __restrict__ A, const __half* __restrict__ Bw,
    const float* __restrict__ bias, void* __restrict__ Cp)
{
    constexpr int nK = KVAL / BK;
    constexpr int Nt = NB * BN;
    extern __shared__ char smem[];
    const uint32_t sb = smem_u32(smem);
    const int tid = threadIdx.x, lane = tid & 31, warp = tid >> 5;
    const int wm = (warp & 1) * 64, wn = (warp >> 1) * 64;
    const int bid = blockIdx.x, G = gridDim.x;
    const int lr = tid >> 3, lc = tid & 7;          // loader row/col

    const int nloc = (NTILE - bid + G - 1) / G;     // tiles owned by this CTA
    const int total_steps = nloc * nK;

    const int mtx  = lane >> 3;
    const int arow = (mtx & 1) * 8 + (lane & 7);
    const int acol = mtx >> 1;
    const int brow = (mtx >> 1) * 8 + (lane & 7);
    const int bcol = mtx & 1;

    uint32_t af[4][4], bq[4][4];                    // persistent frag registers

    // Prologue: issue steps 0 and 1 upfront; land step 0; preload ks0 frags.
    ISSUE_STEP(0);
    asm volatile("cp.async.commit_group;" ::: "memory");
    if (1 < total_steps) ISSUE_STEP(1);
    asm volatile("cp.async.commit_group;" ::: "memory");
    asm volatile("cp.async.wait_group 1;" ::: "memory");
    __syncthreads();
    LOAD_FRAGS(sb, sb + STAGE_A, 0);

    int s = 0;
    for (int tl = 0; tl < nloc; tl++) {
        const int tile = bid + tl * G;
        const int t0 = (tile / NB) * BM, n0 = (tile % NB) * BN;

        float acc[4][8][4];
#pragma unroll
        for (int a = 0; a < 4; a++)
#pragma unroll
            for (int b = 0; b < 8; b++)
#pragma unroll
                for (int c = 0; c < 4; c++) acc[a][b][c] = 0.f;

        for (int kt = 0; kt < nK; kt++, s++) {
            // Per-step precompute for the spread issue of step s+NST-1
            const int sp = s + NST - 1;
            const bool doiss = sp < total_steps;
            const int spc = doiss ? sp : 0;           // safe dummy coords
            const int tile_i = bid + (spc / nK) * G;
            const int kt_i   = spc % nK;
            const int ti0    = (tile_i / NB) * BM;
            const int ni0    = (tile_i % NB) * BN;
            const int ki0    = kt_i * BK;
            const uint32_t iab = sb + (spc % NST) * STAGE_BYTES;
            const uint32_t dstA = iab + SW(lr * 128 + lc * 16);
            const uint32_t dstB = dstA + STAGE_A;     // same swizzle offset
            const __half* srcA = A + (size_t)(ti0 + lr) * KVAL + ki0 + lc * 8;
            const __half* srcB = Bw + (size_t)(ni0 + lr) * KVAL + ki0 + lc * 8;
            const int tapv  = ki0 >> 9;
            const int pbase = (ti0 & (SEQ - 1)) + lr + tapv;
            const __half* srcC = A + (size_t)(ti0 + lr + tapv - 3) * CINC
                               + (ni0 >> 9) * GCH + (ki0 & 511) + lc * 8;

            const uint32_t ab  = sb + (s % NST) * STAGE_BYTES;
            const uint32_t bb  = ab + STAGE_A;
            const uint32_t abn = sb + ((s + 1) % NST) * STAGE_BYTES;
            const uint32_t bbn = abn + STAGE_A;
#pragma unroll
            for (int ks = 0; ks < 4; ks++) {
                // MMAs consume frags loaded one ks earlier
#pragma unroll
                for (int mf = 0; mf < 4; mf++)
#pragma unroll
                    for (int nf = 0; nf < 8; nf++)
                        MMA16(acc[mf][nf], af[mf], &bq[nf >> 1][(nf & 1) * 2]);
                if (ks < 3) LOAD_FRAGS(ab, bb, ks + 1);
                ISSUE_QTR(ks);                         // spread LDGSTS issue
            }

            asm volatile("cp.async.commit_group;" ::: "memory");
            // wait_group 1: stage s+1 landed (committed end of step s-1);
            // never stalls on the group committed just above.
            asm volatile("cp.async.wait_group 1;" ::: "memory");
            __syncthreads();
            LOAD_FRAGS(abn, bbn, 0);                   // next step ks0 frags
        }

        // Epilogue (next step's loads in flight, its ks0 frags in registers)
#pragma unroll
        for (int mf = 0; mf < 4; mf++) {
            int r = t0 + wm + mf * 16 + (lane >> 2);
#pragma unroll
            for (int nf = 0; nf < 8; nf++) {
                int cc = n0 + wn + nf * 8 + (lane & 3) * 2;
                float b0v = __ldg(bias + cc), b1v = __ldg(bias + cc + 1);
                float v0 = acc[mf][nf][0] + b0v;
                float v1 = acc[mf][nf][1] + b1v;
                float v2 = acc[mf][nf][2] + b0v;
                float v3 = acc[mf][nf][3] + b1v;
                if (SILU) {
                    v0 *= 1.f / (1.f + __expf(-v0));
                    v1 *= 1.f / (1.f + __expf(-v1));
                    v2 *= 1.f / (1.f + __expf(-v2));
                    v3 *= 1.f / (1.f + __expf(-v3));
                }
                if (OUTF32) {
                    float* C = (float*)Cp;
                    *(float2*)(C + (size_t)r * Nt + cc)       = make_float2(v0, v1);
                    *(float2*)(C + (size_t)(r + 8) * Nt + cc) = make_float2(v2, v3);
                } else {
                    __half2* C = (__half2*)Cp;
                    C[((size_t)r * Nt + cc) >> 1]       = __floats2half2_rn(v0, v1);
                    C[((size_t)(r + 8) * Nt + cc) >> 1] = __floats2half2_rn(v2, v3);
                }
            }
        }
    }
}

extern "C" void kernel_launch(void* const* d_in, const int* in_sizes, int n_in,
                              void* d_out, int out_size)
{
    const float* x      = (const float*)d_in[0];
    const float* W_in   = (const float*)d_in[1];
    const float* b_in   = (const float*)d_in[2];
    const float* conv_w = (const float*)d_in[3];
    const float* conv_b = (const float*)d_in[4];
    const float* W_out  = (const float*)d_in[5];
    const float* b_out  = (const float*)d_in[6];
    float* out = (float*)d_out;

    __half *x16, *h16, *y16, *wi, *wo, *w2;
    cudaGetSymbolAddress((void**)&x16, g_x16);
    cudaGetSymbolAddress((void**)&h16, g_h16);
    cudaGetSymbolAddress((void**)&y16, g_y16);
    cudaGetSymbolAddress((void**)&wi,  g_wi);
    cudaGetSymbolAddress((void**)&wo,  g_wo);
    cudaGetSymbolAddress((void**)&w2,  g_w2);

    cudaFuncSetAttribute((gemm_p<false, false, false, 2048, 32, 4096>),
                         cudaFuncAttributeMaxDynamicSharedMemorySize, SMEM_TOTAL);
    cudaFuncSetAttribute((gemm_p<true, true, false, 2048, 32, 4096>),
                         cudaFuncAttributeMaxDynamicSharedMemorySize, SMEM_TOTAL);
    cudaFuncSetAttribute((gemm_p<false, false, true, 4096, 16, 2048>),
                         cudaFuncAttributeMaxDynamicSharedMemorySize, SMEM_TOTAL);

    prep_all_kernel<<<(P3 + 255) / 256, 256>>>(x, W_in, W_out, conv_w,
                                               x16, wi, wo, w2);

    // Stage 1: h = x @ W_in^T + b_in               (K=2048, N=4096) -> fp16
    gemm_p<false, false, false, 2048, 32, 4096><<<NCTA, NTHR, SMEM_TOTAL>>>(
        x16, wi, b_in, h16);
    // Stage 2: y = silu(im2col(h) @ w2^T + conv_b) (K=2048, N=4096) -> fp16
    gemm_p<true, true, false, 2048, 32, 4096><<<NCTA, NTHR, SMEM_TOTAL>>>(
        h16, w2, conv_b, y16);
    // Stage 3: out = y @ W_out^T + b_out           (K=4096, N=2048) -> fp32
    gemm_p<false, false, true, 4096, 16, 2048><<<NCTA, NTHR, SMEM_TOTAL>>>(
        y16, wo, b_out, out);
}

// round 12
// speedup vs baseline: 1.2162x; 1.0122x over previous
#include <cuda_runtime.h>
#include <cuda_fp16.h>
#include <stdint.h>

#define SEQ   4096
#define TTOK  16384
#define HID   2048
#define CINC  4096
#define COUTC 4096
#define GCH   512

#define BM 128
#define BN 128
#define BK 64
#define NST 3
#define NTHR 128
#define NCTA 296                              // 2 CTAs/SM * 148 SMs
#define STAGE_A (BM * BK * 2)                 // 16 KB
#define STAGE_BYTES (STAGE_A + BN * BK * 2)   // 32 KB
#define SMEM_TOTAL (NST * STAGE_BYTES)        // 96 KB -> 2 CTAs/SM

// fp16 copies of operands + intermediates (allocation-free rule: __device__ globals)
__device__ __half g_x16[(size_t)TTOK * HID];
__device__ __half g_h16[(size_t)TTOK * CINC];
__device__ __half g_y16[(size_t)TTOK * COUTC];
__device__ __half g_wi [(size_t)CINC * HID];
__device__ __half g_wo [(size_t)HID * COUTC];
__device__ __half g_w2 [(size_t)COUTC * 2048];

// One merged prep launch (4 regions)
#define P0 (TTOK * HID / 2)
#define P1 (P0 + CINC * HID / 2)
#define P2 (P1 + HID * COUTC / 2)
#define P3 (P2 + COUTC * 2048)
__global__ void prep_all_kernel(
    const float* __restrict__ x,  const float* __restrict__ wi_f,
    const float* __restrict__ wo_f, const float* __restrict__ cw,
    __half* __restrict__ x16, __half* __restrict__ wi,
    __half* __restrict__ wo,  __half* __restrict__ w2)
{
    int i = blockIdx.x * blockDim.x + threadIdx.x;
    if (i < P0) {
        float2 v = ((const float2*)x)[i];
        ((__half2*)x16)[i] = __floats2half2_rn(v.x, v.y);
    } else if (i < P1) {
        int j = i - P0;
        float2 v = ((const float2*)wi_f)[j];
        ((__half2*)wi)[j] = __floats2half2_rn(v.x, v.y);
    } else if (i < P2) {
        int j = i - P1;
        float2 v = ((const float2*)wo_f)[j];
        ((__half2*)wo)[j] = __floats2half2_rn(v.x, v.y);
    } else if (i < P3) {
        int j = i - P2;
        int co = j >> 11, r = j & 2047, tap = r >> 9, ci = r & 511;
        w2[j] = __float2half_rn(cw[(co * GCH + ci) * 4 + tap]);
    }
}

__device__ __forceinline__ uint32_t smem_u32(const void* p) {
    uint32_t a;
    asm("{ .reg .u64 t; cvta.to.shared.u64 t, %1; cvt.u32.u64 %0, t; }" : "=r"(a) : "l"(p));
    return a;
}

#define SW(x) ((x) ^ (((x) >> 3) & 0x70))

#define CPA(dst_, src_) \
    asm volatile("cp.async.cg.shared.global [%0], [%1], 16;" :: "r"(dst_), "l"(src_))
#define CPAZ(dst_, src_, sz_) \
    asm volatile("cp.async.cg.shared.global [%0], [%1], 16, %2;" :: "r"(dst_), "l"(src_), "r"(sz_))

#define LDSM4(r_, a_) \
    asm volatile("ldmatrix.sync.aligned.m8n8.x4.shared.b16 {%0,%1,%2,%3}, [%4];" \
        : "=r"((r_)[0]), "=r"((r_)[1]), "=r"((r_)[2]), "=r"((r_)[3]) : "r"(a_))

#define MMA16(c_, a_, b_) \
    asm volatile("mma.sync.aligned.m16n8k16.row.col.f32.f16.f16.f32 " \
        "{%0,%1,%2,%3},{%4,%5,%6,%7},{%8,%9},{%0,%1,%2,%3};" \
        : "+f"((c_)[0]), "+f"((c_)[1]), "+f"((c_)[2]), "+f"((c_)[3]) \
        : "r"((a_)[0]), "r"((a_)[1]), "r"((a_)[2]), "r"((a_)[3]), \
          "r"((b_)[0]), "r"((b_)[1]))

// Load all af/bq fragments for one ks group from stage bases ab_/bb_ (in-place).
#define LOAD_FRAGS(ab_, bb_, ks_) do {                                              \
    _Pragma("unroll")                                                               \
    for (int mf_ = 0; mf_ < 4; mf_++) {                                             \
        int row_ = wm + mf_ * 16 + arow;                                            \
        LDSM4(af[mf_], (ab_) + SW(row_ * 128 + (2 * (ks_) + acol) * 16));           \
    }                                                                               \
    _Pragma("unroll")                                                               \
    for (int pr_ = 0; pr_ < 4; pr_++) {                                             \
        int row_ = wn + pr_ * 16 + brow;                                            \
        LDSM4(bq[pr_], (bb_) + SW(row_ * 128 + (2 * (ks_) + bcol) * 16));           \
    }                                                                               \
} while (0)

// Full-step issue (prologue only). 128 thr: 8 A + 8 B chunks of 16B.
#define ISSUE_STEP(sp_) do {                                                        \
    const int tile_ = bid + ((sp_) / nK) * G;                                       \
    const int kt_   = (sp_) % nK;                                                   \
    const int t0_   = (tile_ / NB) * BM;                                            \
    const int n0_   = (tile_ % NB) * BN;                                            \
    const int k0_   = kt_ * BK;                                                     \
    const uint32_t ab_ = sb + ((sp_) % NST) * STAGE_BYTES;                          \
    const uint32_t bb_ = ab_ + STAGE_A;                                             \
    if (!CONV) {                                                                    \
        _Pragma("unroll")                                                           \
        for (int j = 0; j < 8; j++) {                                               \
            const __half* s_p = A + (size_t)(t0_ + lr + 16 * j) * KVAL + k0_ + lc * 8; \
            CPA(ab_ + SW(lr * 128 + lc * 16) + j * 2048, s_p);                      \
        }                                                                           \
    } else {                                                                        \
        const int tap_ = k0_ >> 9;                                                  \
        const int pb_  = (t0_ & (SEQ - 1)) + lr + tap_;                             \
        const __half* cbase_ = A + (size_t)(t0_ + lr + tap_ - 3) * CINC             \
                             + (n0_ >> 9) * GCH + (k0_ & 511) + lc * 8;             \
        _Pragma("unroll")                                                           \
        for (int j = 0; j < 8; j++) {                                               \
            uint32_t ok_ = (pb_ + 16 * j >= 3) ? 16u : 0u;                          \
            const __half* s_p = ok_ ? cbase_ + (size_t)(16 * j) * CINC : A;         \
            CPAZ(ab_ + SW(lr * 128 + lc * 16) + j * 2048, s_p, ok_);                \
        }                                                                           \
    }                                                                               \
    _Pragma("unroll")                                                               \
    for (int j = 0; j < 8; j++) {                                                   \
        const __half* s_p = Bw + (size_t)(n0_ + lr + 16 * j) * KVAL + k0_ + lc * 8; \
        CPA(bb_ + SW(lr * 128 + lc * 16) + j * 2048, s_p);                          \
    }                                                                               \
} while (0)

// Quarter issue: chunks 2q, 2q+1 of A and B from per-step precomputed bases.
// Swizzle-linearity: +16 rows = +2048 bytes, swizzle bits [7:9] unchanged.
#define ISSUE_QTR(q_) do {                                                          \
    if (doiss) {                                                                    \
        _Pragma("unroll")                                                           \
        for (int j = 2 * (q_); j < 2 * (q_) + 2; j++) {                             \
            if (!CONV) {                                                            \
                CPA(dstA + j * 2048, srcA + (size_t)(16 * j) * KVAL);               \
            } else {                                                                \
                uint32_t ok_ = (pbase + 16 * j >= 3) ? 16u : 0u;                    \
                const __half* s_p = ok_ ? srcC + (size_t)(16 * j) * CINC : A;       \
                CPAZ(dstA + j * 2048, s_p, ok_);                                    \
            }                                                                       \
            CPA(dstB + j * 2048, srcB + (size_t)(16 * j) * KVAL);                   \
        }                                                                           \
    }                                                                               \
} while (0)

// Persistent-CTA GEMM. Cross-barrier frag pipelining + cp.async issue spread
// across the 4 ks MMA blocks; batched per-tile bias load in the epilogue.
template<bool CONV, bool SILU, bool OUTF32, int KVAL, int NB, int NTILE>
__global__ void __launch_bounds__(NTHR, 2) gemm_p(
    const __half* __restrict__ A, const __half* __restrict__ Bw,
    const float* __restrict__ bias, void* __restrict__ Cp)
{
    constexpr int nK = KVAL / BK;
    constexpr int Nt = NB * BN;
    extern __shared__ char smem[];
    const uint32_t sb = smem_u32(smem);
    const int tid = threadIdx.x, lane = tid & 31, warp = tid >> 5;
    const int wm = (warp & 1) * 64, wn = (warp >> 1) * 64;
    const int bid = blockIdx.x, G = gridDim.x;
    const int lr = tid >> 3, lc = tid & 7;          // loader row/col

    const int nloc = (NTILE - bid + G - 1) / G;     // tiles owned by this CTA
    const int total_steps = nloc * nK;

    const int mtx  = lane >> 3;
    const int arow = (mtx & 1) * 8 + (lane & 7);
    const int acol = mtx >> 1;
    const int brow = (mtx >> 1) * 8 + (lane & 7);
    const int bcol = mtx & 1;

    uint32_t af[4][4], bq[4][4];                    // persistent frag registers

    // Prologue: issue steps 0 and 1 upfront; land step 0; preload ks0 frags.
    ISSUE_STEP(0);
    asm volatile("cp.async.commit_group;" ::: "memory");
    if (1 < total_steps) ISSUE_STEP(1);
    asm volatile("cp.async.commit_group;" ::: "memory");
    asm volatile("cp.async.wait_group 1;" ::: "memory");
    __syncthreads();
    LOAD_FRAGS(sb, sb + STAGE_A, 0);

    int s = 0;
    for (int tl = 0; tl < nloc; tl++) {
        const int tile = bid + tl * G;
        const int t0 = (tile / NB) * BM, n0 = (tile % NB) * BN;

        float acc[4][8][4];
#pragma unroll
        for (int a = 0; a < 4; a++)
#pragma unroll
            for (int b = 0; b < 8; b++)
#pragma unroll
                for (int c = 0; c < 4; c++) acc[a][b][c] = 0.f;

        for (int kt = 0; kt < nK; kt++, s++) {
            // Per-step precompute for the spread issue of step s+NST-1
            const int sp = s + NST - 1;
            const bool doiss = sp < total_steps;
            const int spc = doiss ? sp : 0;           // safe dummy coords
            const int tile_i = bid + (spc / nK) * G;
            const int kt_i   = spc % nK;
            const int ti0    = (tile_i / NB) * BM;
            const int ni0    = (tile_i % NB) * BN;
            const int ki0    = kt_i * BK;
            const uint32_t iab = sb + (spc % NST) * STAGE_BYTES;
            const uint32_t dstA = iab + SW(lr * 128 + lc * 16);
            const uint32_t dstB = dstA + STAGE_A;     // same swizzle offset
            const __half* srcA = A + (size_t)(ti0 + lr) * KVAL + ki0 + lc * 8;
            const __half* srcB = Bw + (size_t)(ni0 + lr) * KVAL + ki0 + lc * 8;
            const int tapv  = ki0 >> 9;
            const int pbase = (ti0 & (SEQ - 1)) + lr + tapv;
            const __half* srcC = A + (size_t)(ti0 + lr + tapv - 3) * CINC
                               + (ni0 >> 9) * GCH + (ki0 & 511) + lc * 8;

            const uint32_t ab  = sb + (s % NST) * STAGE_BYTES;
            const uint32_t bb  = ab + STAGE_A;
            const uint32_t abn = sb + ((s + 1) % NST) * STAGE_BYTES;
            const uint32_t bbn = abn + STAGE_A;
#pragma unroll
            for (int ks = 0; ks < 4; ks++) {
                // MMAs consume frags loaded one ks earlier
#pragma unroll
                for (int mf = 0; mf < 4; mf++)
#pragma unroll
                    for (int nf = 0; nf < 8; nf++)
                        MMA16(acc[mf][nf], af[mf], &bq[nf >> 1][(nf & 1) * 2]);
                if (ks < 3) LOAD_FRAGS(ab, bb, ks + 1);
                ISSUE_QTR(ks);                         // spread LDGSTS issue
            }

            asm volatile("cp.async.commit_group;" ::: "memory");
            // wait_group 1: stage s+1 landed (committed end of step s-1);
            // never stalls on the group committed just above.
            asm volatile("cp.async.wait_group 1;" ::: "memory");
            __syncthreads();
            LOAD_FRAGS(abn, bbn, 0);                   // next step ks0 frags
        }

        // Epilogue. Batched bias load: 16 independent LDGs (MLP=16), one
        // latency exposure per tile instead of a dependent stream of 64.
        float bv0[8], bv1[8];
#pragma unroll
        for (int nf = 0; nf < 8; nf++) {
            int cc = n0 + wn + nf * 8 + (lane & 3) * 2;
            bv0[nf] = __ldg(bias + cc);
            bv1[nf] = __ldg(bias + cc + 1);
        }
#pragma unroll
        for (int mf = 0; mf < 4; mf++) {
            int r = t0 + wm + mf * 16 + (lane >> 2);
#pragma unroll
            for (int nf = 0; nf < 8; nf++) {
                int cc = n0 + wn + nf * 8 + (lane & 3) * 2;
                float v0 = acc[mf][nf][0] + bv0[nf];
                float v1 = acc[mf][nf][1] + bv1[nf];
                float v2 = acc[mf][nf][2] + bv0[nf];
                float v3 = acc[mf][nf][3] + bv1[nf];
                if (SILU) {
                    v0 *= 1.f / (1.f + __expf(-v0));
                    v1 *= 1.f / (1.f + __expf(-v1));
                    v2 *= 1.f / (1.f + __expf(-v2));
                    v3 *= 1.f / (1.f + __expf(-v3));
                }
                if (OUTF32) {
                    float* C = (float*)Cp;
                    *(float2*)(C + (size_t)r * Nt + cc)       = make_float2(v0, v1);
                    *(float2*)(C + (size_t)(r + 8) * Nt + cc) = make_float2(v2, v3);
                } else {
                    __half2* C = (__half2*)Cp;
                    C[((size_t)r * Nt + cc) >> 1]       = __floats2half2_rn(v0, v1);
                    C[((size_t)(r + 8) * Nt + cc) >> 1] = __floats2half2_rn(v2, v3);
                }
            }
        }
    }
}

extern "C" void kernel_launch(void* const* d_in, const int* in_sizes, int n_in,
                              void* d_out, int out_size)
{
    const float* x      = (const float*)d_in[0];
    const float* W_in   = (const float*)d_in[1];
    const float* b_in   = (const float*)d_in[2];
    const float* conv_w = (const float*)d_in[3];
    const float* conv_b = (const float*)d_in[4];
    const float* W_out  = (const float*)d_in[5];
    const float* b_out  = (const float*)d_in[6];
    float* out = (float*)d_out;

    __half *x16, *h16, *y16, *wi, *wo, *w2;
    cudaGetSymbolAddress((void**)&x16, g_x16);
    cudaGetSymbolAddress((void**)&h16, g_h16);
    cudaGetSymbolAddress((void**)&y16, g_y16);
    cudaGetSymbolAddress((void**)&wi,  g_wi);
    cudaGetSymbolAddress((void**)&wo,  g_wo);
    cudaGetSymbolAddress((void**)&w2,  g_w2);

    cudaFuncSetAttribute((gemm_p<false, false, false, 2048, 32, 4096>),
                         cudaFuncAttributeMaxDynamicSharedMemorySize, SMEM_TOTAL);
    cudaFuncSetAttribute((gemm_p<true, true, false, 2048, 32, 4096>),
                         cudaFuncAttributeMaxDynamicSharedMemorySize, SMEM_TOTAL);
    cudaFuncSetAttribute((gemm_p<false, false, true, 4096, 16, 2048>),
                         cudaFuncAttributeMaxDynamicSharedMemorySize, SMEM_TOTAL);

    prep_all_kernel<<<(P3 + 255) / 256, 256>>>(x, W_in, W_out, conv_w,
                                               x16, wi, wo, w2);

    // Stage 1: h = x @ W_in^T + b_in               (K=2048, N=4096) -> fp16
    gemm_p<false, false, false, 2048, 32, 4096><<<NCTA, NTHR, SMEM_TOTAL>>>(
        x16, wi, b_in, h16);
    // Stage 2: y = silu(im2col(h) @ w2^T + conv_b) (K=2048, N=4096) -> fp16
    gemm_p<true, true, false, 2048, 32, 4096><<<NCTA, NTHR, SMEM_TOTAL>>>(
        h16, w2, conv_b, y16);
    // Stage 3: out = y @ W_out^T + b_out           (K=4096, N=2048) -> fp32
    gemm_p<false, false, true, 4096, 16, 2048><<<NCTA, NTHR, SMEM_TOTAL>>>(
        y16, wo, b_out, out);
}

// round 13
// speedup vs baseline: 1.2296x; 1.0110x over previous
#include <cuda_runtime.h>
#include <cuda_fp16.h>
#include <stdint.h>

#define SEQ   4096
#define TTOK  16384
#define HID   2048
#define CINC  4096
#define COUTC 4096
#define GCH   512

#define BM 128
#define BN 128
#define BK 64
#define NST 3
#define NTHR 128
#define NCTA 296                              // 2 CTAs/SM * 148 SMs
#define STAGE_A (BM * BK * 2)                 // 16 KB
#define STAGE_BYTES (STAGE_A + BN * BK * 2)   // 32 KB
#define SMEM_TOTAL (NST * STAGE_BYTES + 16)   // 96 KB ring + ctrl word

// fp16 copies of operands + intermediates (allocation-free rule: __device__ globals)
__device__ __half g_x16[(size_t)TTOK * HID];
__device__ __half g_h16[(size_t)TTOK * CINC];
__device__ __half g_y16[(size_t)TTOK * COUTC];
__device__ __half g_wi [(size_t)CINC * HID];
__device__ __half g_wo [(size_t)HID * COUTC];
__device__ __half g_w2 [(size_t)COUTC * 2048];
__device__ unsigned g_ctr[4];                 // per-stage tile counters

// One merged prep launch (4 regions). Region 3: one thread per (co,ci),
// float4 read of all 4 taps (100% sector efficiency), 4 strided half writes.
#define P0 (TTOK * HID / 2)
#define P1 (P0 + CINC * HID / 2)
#define P2 (P1 + HID * COUTC / 2)
#define P3 (P2 + COUTC * GCH)
__global__ void prep_all_kernel(
    const float* __restrict__ x,  const float* __restrict__ wi_f,
    const float* __restrict__ wo_f, const float* __restrict__ cw,
    __half* __restrict__ x16, __half* __restrict__ wi,
    __half* __restrict__ wo,  __half* __restrict__ w2)
{
    int i = blockIdx.x * blockDim.x + threadIdx.x;
    if (i == 0) { g_ctr[0] = 0; g_ctr[1] = 0; g_ctr[2] = 0; }  // stealing ctrs
    if (i < P0) {
        float2 v = ((const float2*)x)[i];
        ((__half2*)x16)[i] = __floats2half2_rn(v.x, v.y);
    } else if (i < P1) {
        int j = i - P0;
        float2 v = ((const float2*)wi_f)[j];
        ((__half2*)wi)[j] = __floats2half2_rn(v.x, v.y);
    } else if (i < P2) {
        int j = i - P1;
        float2 v = ((const float2*)wo_f)[j];
        ((__half2*)wo)[j] = __floats2half2_rn(v.x, v.y);
    } else if (i < P3) {
        int j = i - P2;
        int co = j >> 9, ci = j & 511;
        float4 v = *(const float4*)(cw + (size_t)j * 4);
        __half* base = w2 + (size_t)co * 2048 + ci;
        base[0]    = __float2half_rn(v.x);
        base[512]  = __float2half_rn(v.y);
        base[1024] = __float2half_rn(v.z);
        base[1536] = __float2half_rn(v.w);
    }
}

__device__ __forceinline__ uint32_t smem_u32(const void* p) {
    uint32_t a;
    asm("{ .reg .u64 t; cvta.to.shared.u64 t, %1; cvt.u32.u64 %0, t; }" : "=r"(a) : "l"(p));
    return a;
}

#define SW(x) ((x) ^ (((x) >> 3) & 0x70))

#define CPA(dst_, src_) \
    asm volatile("cp.async.cg.shared.global [%0], [%1], 16;" :: "r"(dst_), "l"(src_))
#define CPAZ(dst_, src_, sz_) \
    asm volatile("cp.async.cg.shared.global [%0], [%1], 16, %2;" :: "r"(dst_), "l"(src_), "r"(sz_))

#define LDSM4(r_, a_) \
    asm volatile("ldmatrix.sync.aligned.m8n8.x4.shared.b16 {%0,%1,%2,%3}, [%4];" \
        : "=r"((r_)[0]), "=r"((r_)[1]), "=r"((r_)[2]), "=r"((r_)[3]) : "r"(a_))

#define MMA16(c_, a_, b_) \
    asm volatile("mma.sync.aligned.m16n8k16.row.col.f32.f16.f16.f32 " \
        "{%0,%1,%2,%3},{%4,%5,%6,%7},{%8,%9},{%0,%1,%2,%3};" \
        : "+f"((c_)[0]), "+f"((c_)[1]), "+f"((c_)[2]), "+f"((c_)[3]) \
        : "r"((a_)[0]), "r"((a_)[1]), "r"((a_)[2]), "r"((a_)[3]), \
          "r"((b_)[0]), "r"((b_)[1]))

// Load all af/bq fragments for one ks group from stage bases ab_/bb_ (in-place).
#define LOAD_FRAGS(ab_, bb_, ks_) do {                                              \
    _Pragma("unroll")                                                               \
    for (int mf_ = 0; mf_ < 4; mf_++) {                                             \
        int row_ = wm + mf_ * 16 + arow;                                            \
        LDSM4(af[mf_], (ab_) + SW(row_ * 128 + (2 * (ks_) + acol) * 16));           \
    }                                                                               \
    _Pragma("unroll")                                                               \
    for (int pr_ = 0; pr_ < 4; pr_++) {                                             \
        int row_ = wn + pr_ * 16 + brow;                                            \
        LDSM4(bq[pr_], (bb_) + SW(row_ * 128 + (2 * (ks_) + bcol) * 16));           \
    }                                                                               \
} while (0)

// Full-step issue into ring slot slot_ for (tile_, kt_). Prologue only.
#define ISSUE_TS(tile_, kt_, slot_) do {                                            \
    const int t0_ = ((tile_) / NB) * BM;                                            \
    const int n0_ = ((tile_) % NB) * BN;                                            \
    const int k0_ = (kt_) * BK;                                                     \
    const uint32_t ab_ = sb + (slot_) * STAGE_BYTES;                                \
    const uint32_t bb_ = ab_ + STAGE_A;                                             \
    if (!CONV) {                                                                    \
        _Pragma("unroll")                                                           \
        for (int j = 0; j < 8; j++) {                                               \
            const __half* s_p = A + (size_t)(t0_ + lr + 16 * j) * KVAL + k0_ + lc * 8; \
            CPA(ab_ + SW(lr * 128 + lc * 16) + j * 2048, s_p);                      \
        }                                                                           \
    } else {                                                                        \
        const int tap_ = k0_ >> 9;                                                  \
        const int pb_  = (t0_ & (SEQ - 1)) + lr + tap_;                             \
        const __half* cbase_ = A + (size_t)(t0_ + lr + tap_ - 3) * CINC             \
                             + (n0_ >> 9) * GCH + (k0_ & 511) + lc * 8;             \
        _Pragma("unroll")                                                           \
        for (int j = 0; j < 8; j++) {                                               \
            uint32_t ok_ = (pb_ + 16 * j >= 3) ? 16u : 0u;                          \
            const __half* s_p = ok_ ? cbase_ + (size_t)(16 * j) * CINC : A;         \
            CPAZ(ab_ + SW(lr * 128 + lc * 16) + j * 2048, s_p, ok_);                \
        }                                                                           \
    }                                                                               \
    _Pragma("unroll")                                                               \
    for (int j = 0; j < 8; j++) {                                                   \
        const __half* s_p = Bw + (size_t)(n0_ + lr + 16 * j) * KVAL + k0_ + lc * 8; \
        CPA(bb_ + SW(lr * 128 + lc * 16) + j * 2048, s_p);                          \
    }                                                                               \
} while (0)

// Quarter issue: chunks 2q, 2q+1 of A and B from per-step precomputed bases.
// Swizzle-linearity: +16 rows = +2048 bytes, swizzle bits [7:9] unchanged.
#define ISSUE_QTR(q_) do {                                                          \
    if (doiss) {                                                                    \
        _Pragma("unroll")                                                           \
        for (int j = 2 * (q_); j < 2 * (q_) + 2; j++) {                             \
            if (!CONV) {                                                            \
                CPA(dstA + j * 2048, srcA + (size_t)(16 * j) * KVAL);               \
            } else {                                                                \
                uint32_t ok_ = (pbase + 16 * j >= 3) ? 16u : 0u;                    \
                const __half* s_p = ok_ ? srcC + (size_t)(16 * j) * CINC : A;       \
                CPAZ(dstA + j * 2048, s_p, ok_);                                    \
            }                                                                       \
            CPA(dstB + j * 2048, srcB + (size_t)(16 * j) * KVAL);                   \
        }                                                                           \
    }                                                                               \
} while (0)

// Persistent-CTA GEMM with dynamic tile stealing (two-deep claim cur/nxt),
// cross-barrier frag pipelining, spread cp.async issue, batched bias epilogue.
template<bool CONV, bool SILU, bool OUTF32, int KVAL, int NB, int NTILE, int SID>
__global__ void __launch_bounds__(NTHR, 2) gemm_p(
    const __half* __restrict__ A, const __half* __restrict__ Bw,
    const float* __restrict__ bias, void* __restrict__ Cp)
{
    constexpr int nK = KVAL / BK;
    constexpr int Nt = NB * BN;
    extern __shared__ char smem[];
    const uint32_t sb = smem_u32(smem);
    unsigned* ctrl = (unsigned*)(smem + NST * STAGE_BYTES);
    const int tid = threadIdx.x, lane = tid & 31, warp = tid >> 5;
    const int wm = (warp & 1) * 64, wn = (warp >> 1) * 64;
    const int lr = tid >> 3, lc = tid & 7;          // loader row/col

    const int mtx  = lane >> 3;
    const int arow = (mtx & 1) * 8 + (lane & 7);
    const int acol = mtx >> 1;
    const int brow = (mtx >> 1) * 8 + (lane & 7);
    const int bcol = mtx & 1;

    uint32_t af[4][4], bq[4][4];                    // persistent frag registers

    // Claim first tile; issue its steps 0,1; claim second tile.
    if (tid == 0) ctrl[0] = atomicAdd(&g_ctr[SID], 1u);
    __syncthreads();
    int cur = (int)ctrl[0];
    __syncthreads();                                 // all read before overwrite
    if (tid == 0) ctrl[0] = atomicAdd(&g_ctr[SID], 1u);
    ISSUE_TS(cur, 0, 0);
    asm volatile("cp.async.commit_group;" ::: "memory");
    ISSUE_TS(cur, 1, 1);
    asm volatile("cp.async.commit_group;" ::: "memory");
    asm volatile("cp.async.wait_group 1;" ::: "memory");
    __syncthreads();
    int nxt = (int)ctrl[0];
    LOAD_FRAGS(sb, sb + STAGE_A, 0);

    int s = 0;
    while (cur < NTILE) {
        const int t0 = (cur / NB) * BM, n0 = (cur % NB) * BN;

        float acc[4][8][4];
#pragma unroll
        for (int a = 0; a < 4; a++)
#pragma unroll
            for (int b = 0; b < 8; b++)
#pragma unroll
                for (int c = 0; c < 4; c++) acc[a][b][c] = 0.f;

        for (int kt = 0; kt < nK; kt++, s++) {
            // Precompute spread-issue for step kt+2 (this tile or next)
            const int kt2 = kt + 2;
            const bool in_cur = kt2 < nK;
            const int til_i = in_cur ? cur : nxt;
            const int kt_i  = in_cur ? kt2 : kt2 - nK;
            const bool doiss = til_i < NTILE;
            const int tsafe = doiss ? til_i : 0;
            const int ti0 = (tsafe / NB) * BM;
            const int ni0 = (tsafe % NB) * BN;
            const int ki0 = kt_i * BK;
            const uint32_t iab = sb + ((s + 2) % NST) * STAGE_BYTES;
            const uint32_t dstA = iab + SW(lr * 128 + lc * 16);
            const uint32_t dstB = dstA + STAGE_A;    // same swizzle offset
            const __half* srcA = A + (size_t)(ti0 + lr) * KVAL + ki0 + lc * 8;
            const __half* srcB = Bw + (size_t)(ni0 + lr) * KVAL + ki0 + lc * 8;
            const int tapv  = ki0 >> 9;
            const int pbase = (ti0 & (SEQ - 1)) + lr + tapv;
            const __half* srcC = A + (size_t)(ti0 + lr + tapv - 3) * CINC
                               + (ni0 >> 9) * GCH + (ki0 & 511) + lc * 8;

            const uint32_t ab  = sb + (s % NST) * STAGE_BYTES;
            const uint32_t bb  = ab + STAGE_A;
            const uint32_t abn = sb + ((s + 1) % NST) * STAGE_BYTES;
            const uint32_t bbn = abn + STAGE_A;
#pragma unroll
            for (int ks = 0; ks < 4; ks++) {
                // MMAs consume frags loaded one ks earlier
#pragma unroll
                for (int mf = 0; mf < 4; mf++)
#pragma unroll
                    for (int nf = 0; nf < 8; nf++)
                        MMA16(acc[mf][nf], af[mf], &bq[nf >> 1][(nf & 1) * 2]);
                if (ks < 3) LOAD_FRAGS(ab, bb, ks + 1);
                ISSUE_QTR(ks);                       // spread LDGSTS issue
            }

            asm volatile("cp.async.commit_group;" ::: "memory");
            // wait_group 1: stage s+1 landed (committed end of step s-1);
            // never stalls on the group committed just above.
            asm volatile("cp.async.wait_group 1;" ::: "memory");
            __syncthreads();
            LOAD_FRAGS(abn, bbn, 0);                 // next step ks0 frags
        }

        // Claim the tile after nxt (epilogue below overlaps the atomic's
        // latency; all threads read ctrl only after the post-epilogue bar).
        if (tid == 0) ctrl[0] = atomicAdd(&g_ctr[SID], 1u);

        // Epilogue. Batched bias: 16 independent LDGs, one latency exposure.
        float bv0[8], bv1[8];
#pragma unroll
        for (int nf = 0; nf < 8; nf++) {
            int cc = n0 + wn + nf * 8 + (lane & 3) * 2;
            bv0[nf] = __ldg(bias + cc);
            bv1[nf] = __ldg(bias + cc + 1);
        }
#pragma unroll
        for (int mf = 0; mf < 4; mf++) {
            int r = t0 + wm + mf * 16 + (lane >> 2);
#pragma unroll
            for (int nf = 0; nf < 8; nf++) {
                int cc = n0 + wn + nf * 8 + (lane & 3) * 2;
                float v0 = acc[mf][nf][0] + bv0[nf];
                float v1 = acc[mf][nf][1] + bv1[nf];
                float v2 = acc[mf][nf][2] + bv0[nf];
                float v3 = acc[mf][nf][3] + bv1[nf];
                if (SILU) {
                    v0 *= 1.f / (1.f + __expf(-v0));
                    v1 *= 1.f / (1.f + __expf(-v1));
                    v2 *= 1.f / (1.f + __expf(-v2));
                    v3 *= 1.f / (1.f + __expf(-v3));
                }
                if (OUTF32) {
                    float* C = (float*)Cp;
                    *(float2*)(C + (size_t)r * Nt + cc)       = make_float2(v0, v1);
                    *(float2*)(C + (size_t)(r + 8) * Nt + cc) = make_float2(v2, v3);
                } else {
                    __half2* C = (__half2*)Cp;
                    C[((size_t)r * Nt + cc) >> 1]       = __floats2half2_rn(v0, v1);
                    C[((size_t)(r + 8) * Nt + cc) >> 1] = __floats2half2_rn(v2, v3);
                }
            }
        }

        __syncthreads();
        cur = nxt;
        nxt = (int)ctrl[0];
    }
}

extern "C" void kernel_launch(void* const* d_in, const int* in_sizes, int n_in,
                              void* d_out, int out_size)
{
    const float* x      = (const float*)d_in[0];
    const float* W_in   = (const float*)d_in[1];
    const float* b_in   = (const float*)d_in[2];
    const float* conv_w = (const float*)d_in[3];
    const float* conv_b = (const float*)d_in[4];
    const float* W_out  = (const float*)d_in[5];
    const float* b_out  = (const float*)d_in[6];
    float* out = (float*)d_out;

    __half *x16, *h16, *y16, *wi, *wo, *w2;
    cudaGetSymbolAddress((void**)&x16, g_x16);
    cudaGetSymbolAddress((void**)&h16, g_h16);
    cudaGetSymbolAddress((void**)&y16, g_y16);
    cudaGetSymbolAddress((void**)&wi,  g_wi);
    cudaGetSymbolAddress((void**)&wo,  g_wo);
    cudaGetSymbolAddress((void**)&w2,  g_w2);

    cudaFuncSetAttribute((gemm_p<false, false, false, 2048, 32, 4096, 0>),
                         cudaFuncAttributeMaxDynamicSharedMemorySize, SMEM_TOTAL);
    cudaFuncSetAttribute((gemm_p<true, true, false, 2048, 32, 4096, 1>),
                         cudaFuncAttributeMaxDynamicSharedMemorySize, SMEM_TOTAL);
    cudaFuncSetAttribute((gemm_p<false, false, true, 4096, 16, 2048, 2>),
                         cudaFuncAttributeMaxDynamicSharedMemorySize, SMEM_TOTAL);

    prep_all_kernel<<<(P3 + 255) / 256, 256>>>(x, W_in, W_out, conv_w,
                                               x16, wi, wo, w2);

    // Stage 1: h = x @ W_in^T + b_in               (K=2048, N=4096) -> fp16
    gemm_p<false, false, false, 2048, 32, 4096, 0><<<NCTA, NTHR, SMEM_TOTAL>>>(
        x16, wi, b_in, h16);
    // Stage 2: y = silu(im2col(h) @ w2^T + conv_b) (K=2048, N=4096) -> fp16
    gemm_p<true, true, false, 2048, 32, 4096, 1><<<NCTA, NTHR, SMEM_TOTAL>>>(
        h16, w2, conv_b, y16);
    // Stage 3: out = y @ W_out^T + b_out           (K=4096, N=2048) -> fp32
    gemm_p<false, false, true, 4096, 16, 2048, 2><<<NCTA, NTHR, SMEM_TOTAL>>>(
        y16, wo, b_out, out);
}

// round 17
// speedup vs baseline: 1.2473x; 1.0144x over previous
#include <cuda_runtime.h>
#include <cuda_fp16.h>
#include <stdint.h>

#define SEQ   4096
#define TTOK  16384
#define HID   2048
#define CINC  4096
#define COUTC 4096
#define GCH   512

#define BM 128
#define BN 128
#define BK 64
#define NST 3
#define NTHR 128
#define NCTA 296                              // 2 CTAs/SM * 148 SMs
#define STAGE_A (BM * BK * 2)                 // 16 KB
#define STAGE_BYTES (STAGE_A + BN * BK * 2)   // 32 KB
#define SMEM_TOTAL (NST * STAGE_BYTES + 16)   // 96 KB ring + ctrl word

// fp16 copies of operands + intermediates (allocation-free rule: __device__ globals)
__device__ __half g_x16[(size_t)TTOK * HID];
__device__ __half g_h16[(size_t)TTOK * CINC];
__device__ __half g_y16[(size_t)TTOK * COUTC];
__device__ __half g_wi [(size_t)CINC * HID];
__device__ __half g_wo [(size_t)HID * COUTC];
__device__ __half g_w2 [(size_t)COUTC * 2048];
__device__ unsigned g_ctr[4];                 // per-stage tile counters

// One merged prep launch (4 regions). Region 3: one thread per (co,ci),
// float4 read of all 4 taps (100% sector efficiency), 4 strided half writes.
#define P0 (TTOK * HID / 2)
#define P1 (P0 + CINC * HID / 2)
#define P2 (P1 + HID * COUTC / 2)
#define P3 (P2 + COUTC * GCH)
__global__ void prep_all_kernel(
    const float* __restrict__ x,  const float* __restrict__ wi_f,
    const float* __restrict__ wo_f, const float* __restrict__ cw,
    __half* __restrict__ x16, __half* __restrict__ wi,
    __half* __restrict__ wo,  __half* __restrict__ w2)
{
    int i = blockIdx.x * blockDim.x + threadIdx.x;
    if (i == 0) { g_ctr[0] = 0; g_ctr[1] = 0; g_ctr[2] = 0; }  // stealing ctrs
    if (i < P0) {
        float2 v = ((const float2*)x)[i];
        ((__half2*)x16)[i] = __floats2half2_rn(v.x, v.y);
    } else if (i < P1) {
        int j = i - P0;
        float2 v = ((const float2*)wi_f)[j];
        ((__half2*)wi)[j] = __floats2half2_rn(v.x, v.y);
    } else if (i < P2) {
        int j = i - P1;
        float2 v = ((const float2*)wo_f)[j];
        ((__half2*)wo)[j] = __floats2half2_rn(v.x, v.y);
    } else if (i < P3) {
        int j = i - P2;
        int co = j >> 9, ci = j & 511;
        float4 v = *(const float4*)(cw + (size_t)j * 4);
        __half* base = w2 + (size_t)co * 2048 + ci;
        base[0]    = __float2half_rn(v.x);
        base[512]  = __float2half_rn(v.y);
        base[1024] = __float2half_rn(v.z);
        base[1536] = __float2half_rn(v.w);
    }
}

__device__ __forceinline__ uint32_t smem_u32(const void* p) {
    uint32_t a;
    asm("{ .reg .u64 t; cvta.to.shared.u64 t, %1; cvt.u32.u64 %0, t; }" : "=r"(a) : "l"(p));
    return a;
}

#define SW(x) ((x) ^ (((x) >> 3) & 0x70))

#define CPA(dst_, src_) \
    asm volatile("cp.async.cg.shared.global [%0], [%1], 16;" :: "r"(dst_), "l"(src_))
#define CPAZ(dst_, src_, sz_) \
    asm volatile("cp.async.cg.shared.global [%0], [%1], 16, %2;" :: "r"(dst_), "l"(src_), "r"(sz_))

#define LDSM4(r_, a_) \
    asm volatile("ldmatrix.sync.aligned.m8n8.x4.shared.b16 {%0,%1,%2,%3}, [%4];" \
        : "=r"((r_)[0]), "=r"((r_)[1]), "=r"((r_)[2]), "=r"((r_)[3]) : "r"(a_))

#define MMA16(c_, a_, b_) \
    asm volatile("mma.sync.aligned.m16n8k16.row.col.f32.f16.f16.f32 " \
        "{%0,%1,%2,%3},{%4,%5,%6,%7},{%8,%9},{%0,%1,%2,%3};" \
        : "+f"((c_)[0]), "+f"((c_)[1]), "+f"((c_)[2]), "+f"((c_)[3]) \
        : "r"((a_)[0]), "r"((a_)[1]), "r"((a_)[2]), "r"((a_)[3]), \
          "r"((b_)[0]), "r"((b_)[1]))

// Load all af/bq fragments for one ks group from stage bases ab_/bb_ (in-place).
#define LOAD_FRAGS(ab_, bb_, ks_) do {                                              \
    _Pragma("unroll")                                                               \
    for (int mf_ = 0; mf_ < 4; mf_++) {                                             \
        int row_ = wm + mf_ * 16 + arow;                                            \
        LDSM4(af[mf_], (ab_) + SW(row_ * 128 + (2 * (ks_) + acol) * 16));           \
    }                                                                               \
    _Pragma("unroll")                                                               \
    for (int pr_ = 0; pr_ < 4; pr_++) {                                             \
        int row_ = wn + pr_ * 16 + brow;                                            \
        LDSM4(bq[pr_], (bb_) + SW(row_ * 128 + (2 * (ks_) + bcol) * 16));           \
    }                                                                               \
} while (0)

// Full-step issue into ring slot slot_ for (tile_, kt_). Prologue only.
#define ISSUE_TS(tile_, kt_, slot_) do {                                            \
    const int t0_ = ((tile_) / NB) * BM;                                            \
    const int n0_ = ((tile_) % NB) * BN;                                            \
    const int k0_ = (kt_) * BK;                                                     \
    const uint32_t ab_ = sb + (slot_) * STAGE_BYTES;                                \
    const uint32_t bb_ = ab_ + STAGE_A;                                             \
    if (!CONV) {                                                                    \
        _Pragma("unroll")                                                           \
        for (int j = 0; j < 8; j++) {                                               \
            const __half* s_p = A + (size_t)(t0_ + lr + 16 * j) * KVAL + k0_ + lc * 8; \
            CPA(ab_ + SW(lr * 128 + lc * 16) + j * 2048, s_p);                      \
        }                                                                           \
    } else {                                                                        \
        const int tap_ = k0_ >> 9;                                                  \
        const int pb_  = (t0_ & (SEQ - 1)) + lr + tap_;                             \
        const __half* cbase_ = A + (size_t)(t0_ + lr + tap_ - 3) * CINC             \
                             + (n0_ >> 9) * GCH + (k0_ & 511) + lc * 8;             \
        _Pragma("unroll")                                                           \
        for (int j = 0; j < 8; j++) {                                               \
            uint32_t ok_ = (pb_ + 16 * j >= 3) ? 16u : 0u;                          \
            const __half* s_p = ok_ ? cbase_ + (size_t)(16 * j) * CINC : A;         \
            CPAZ(ab_ + SW(lr * 128 + lc * 16) + j * 2048, s_p, ok_);                \
        }                                                                           \
    }                                                                               \
    _Pragma("unroll")                                                               \
    for (int j = 0; j < 8; j++) {                                                   \
        const __half* s_p = Bw + (size_t)(n0_ + lr + 16 * j) * KVAL + k0_ + lc * 8; \
        CPA(bb_ + SW(lr * 128 + lc * 16) + j * 2048, s_p);                          \
    }                                                                               \
} while (0)

// Quarter issue: chunks 2q, 2q+1 of A and B from per-step precomputed bases.
// Swizzle-linearity: +16 rows = +2048 bytes, swizzle bits [7:9] unchanged.
#define ISSUE_QTR(q_) do {                                                          \
    if (doiss) {                                                                    \
        _Pragma("unroll")                                                           \
        for (int j = 2 * (q_); j < 2 * (q_) + 2; j++) {                             \
            if (!CONV) {                                                            \
                CPA(dstA + j * 2048, srcA + (size_t)(16 * j) * KVAL);               \
            } else {                                                                \
                uint32_t ok_ = (pbase + 16 * j >= 3) ? 16u : 0u;                    \
                const __half* s_p = ok_ ? srcC + (size_t)(16 * j) * CINC : A;       \
                CPAZ(dstA + j * 2048, s_p, ok_);                                    \
            }                                                                       \
            CPA(dstB + j * 2048, srcB + (size_t)(16 * j) * KVAL);                   \
        }                                                                           \
    }                                                                               \
} while (0)

// Persistent-CTA GEMM, dynamic tile stealing. Step layout:
//   ks0..ks2: MMA + frag reload + spread issue
//   wait_group 0 + __syncthreads()   <- stage s+1 now visible from ALL threads
//   ks3: MMA (regs only) + preload next-step ks0 frags from stage s+1 (safe,
//        post-barrier) + QTR3 + commit
// The barrier sits between ks2 and ks3, so the preload's LDSM latency hides
// under ks3's MMA block, and the next step begins with operands in registers.
template<bool CONV, bool SILU, bool OUTF32, int KVAL, int NB, int NTILE, int SID>
__global__ void __launch_bounds__(NTHR, 2) gemm_p(
    const __half* __restrict__ A, const __half* __restrict__ Bw,
    const float* __restrict__ bias, void* __restrict__ Cp)
{
    constexpr int nK = KVAL / BK;
    constexpr int Nt = NB * BN;
    extern __shared__ char smem[];
    const uint32_t sb = smem_u32(smem);
    unsigned* ctrl = (unsigned*)(smem + NST * STAGE_BYTES);
    const int tid = threadIdx.x, lane = tid & 31, warp = tid >> 5;
    const int wm = (warp & 1) * 64, wn = (warp >> 1) * 64;
    const int lr = tid >> 3, lc = tid & 7;          // loader row/col

    const int mtx  = lane >> 3;
    const int arow = (mtx & 1) * 8 + (lane & 7);
    const int acol = mtx >> 1;
    const int brow = (mtx >> 1) * 8 + (lane & 7);
    const int bcol = mtx & 1;

    uint32_t af[4][4], bq[4][4];                    // persistent frag registers

    // Claim first tile; issue its steps 0,1; claim second tile.
    if (tid == 0) ctrl[0] = atomicAdd(&g_ctr[SID], 1u);
    __syncthreads();
    int cur = (int)ctrl[0];
    __syncthreads();                                 // all read before overwrite
    if (tid == 0) ctrl[0] = atomicAdd(&g_ctr[SID], 1u);
    ISSUE_TS(cur, 0, 0);
    asm volatile("cp.async.commit_group;" ::: "memory");
    ISSUE_TS(cur, 1, 1);
    asm volatile("cp.async.commit_group;" ::: "memory");
    asm volatile("cp.async.wait_group 1;" ::: "memory");
    __syncthreads();
    int nxt = (int)ctrl[0];
    LOAD_FRAGS(sb, sb + STAGE_A, 0);

    int s = 0;
    while (cur < NTILE) {
        const int t0 = (cur / NB) * BM, n0 = (cur % NB) * BN;

        float acc[4][8][4];
#pragma unroll
        for (int a = 0; a < 4; a++)
#pragma unroll
            for (int b = 0; b < 8; b++)
#pragma unroll
                for (int c = 0; c < 4; c++) acc[a][b][c] = 0.f;

        for (int kt = 0; kt < nK; kt++, s++) {
            // Precompute spread-issue for step kt+2 (this tile or next)
            const int kt2 = kt + 2;
            const bool in_cur = kt2 < nK;
            const int til_i = in_cur ? cur : nxt;
            const int kt_i  = in_cur ? kt2 : kt2 - nK;
            const bool doiss = til_i < NTILE;
            const int tsafe = doiss ? til_i : 0;
            const int ti0 = (tsafe / NB) * BM;
            const int ni0 = (tsafe % NB) * BN;
            const int ki0 = kt_i * BK;
            const uint32_t iab = sb + ((s + 2) % NST) * STAGE_BYTES;
            const uint32_t dstA = iab + SW(lr * 128 + lc * 16);
            const uint32_t dstB = dstA + STAGE_A;    // same swizzle offset
            const __half* srcA = A + (size_t)(ti0 + lr) * KVAL + ki0 + lc * 8;
            const __half* srcB = Bw + (size_t)(ni0 + lr) * KVAL + ki0 + lc * 8;
            const int tapv  = ki0 >> 9;
            const int pbase = (ti0 & (SEQ - 1)) + lr + tapv;
            const __half* srcC = A + (size_t)(ti0 + lr + tapv - 3) * CINC
                               + (ni0 >> 9) * GCH + (ki0 & 511) + lc * 8;

            const uint32_t ab  = sb + (s % NST) * STAGE_BYTES;
            const uint32_t bb  = ab + STAGE_A;
            const uint32_t abn = sb + ((s + 1) % NST) * STAGE_BYTES;
            const uint32_t bbn = abn + STAGE_A;
#pragma unroll
            for (int ks = 0; ks < 4; ks++) {
                // MMAs consume frags loaded one ks earlier
#pragma unroll
                for (int mf = 0; mf < 4; mf++)
#pragma unroll
                    for (int nf = 0; nf < 8; nf++)
                        MMA16(acc[mf][nf], af[mf], &bq[nf >> 1][(nf & 1) * 2]);
                if (ks < 3) {
                    LOAD_FRAGS(ab, bb, ks + 1);     // last stage-s LDS at ks==2
                    ISSUE_QTR(ks);
                    if (ks == 2) {
                        // Own stage-s+1 group committed end of step s-1 (near
                        // no-op wait); barrier makes ALL threads' copies
                        // visible before the ks3 preload reads stage s+1.
                        asm volatile("cp.async.wait_group 0;" ::: "memory");
                        __syncthreads();
                    }
                } else {
                    LOAD_FRAGS(abn, bbn, 0);        // safe: post-barrier
                    ISSUE_QTR(3);
                }
            }
            asm volatile("cp.async.commit_group;" ::: "memory");
        }

        // Claim the tile after nxt (epilogue below overlaps the atomic's
        // latency; all threads read ctrl only after the post-epilogue bar).
        if (tid == 0) ctrl[0] = atomicAdd(&g_ctr[SID], 1u);

        // Epilogue. Batched bias: 16 independent LDGs, one latency exposure.
        float bv0[8], bv1[8];
#pragma unroll
        for (int nf = 0; nf < 8; nf++) {
            int cc = n0 + wn + nf * 8 + (lane & 3) * 2;
            bv0[nf] = __ldg(bias + cc);
            bv1[nf] = __ldg(bias + cc + 1);
        }
#pragma unroll
        for (int mf = 0; mf < 4; mf++) {
            int r = t0 + wm + mf * 16 + (lane >> 2);
#pragma unroll
            for (int nf = 0; nf < 8; nf++) {
                int cc = n0 + wn + nf * 8 + (lane & 3) * 2;
                float v0 = acc[mf][nf][0] + bv0[nf];
                float v1 = acc[mf][nf][1] + bv1[nf];
                float v2 = acc[mf][nf][2] + bv0[nf];
                float v3 = acc[mf][nf][3] + bv1[nf];
                if (SILU) {
                    v0 *= 1.f / (1.f + __expf(-v0));
                    v1 *= 1.f / (1.f + __expf(-v1));
                    v2 *= 1.f / (1.f + __expf(-v2));
                    v3 *= 1.f / (1.f + __expf(-v3));
                }
                if (OUTF32) {
                    float* C = (float*)Cp;
                    *(float2*)(C + (size_t)r * Nt + cc)       = make_float2(v0, v1);
                    *(float2*)(C + (size_t)(r + 8) * Nt + cc) = make_float2(v2, v3);
                } else {
                    __half2* C = (__half2*)Cp;
                    C[((size_t)r * Nt + cc) >> 1]       = __floats2half2_rn(v0, v1);
                    C[((size_t)(r + 8) * Nt + cc) >> 1] = __floats2half2_rn(v2, v3);
                }
            }
        }

        __syncthreads();
        cur = nxt;
        nxt = (int)ctrl[0];
    }
}

extern "C" void kernel_launch(void* const* d_in, const int* in_sizes, int n_in,
                              void* d_out, int out_size)
{
    const float* x      = (const float*)d_in[0];
    const float* W_in   = (const float*)d_in[1];
    const float* b_in   = (const float*)d_in[2];
    const float* conv_w = (const float*)d_in[3];
    const float* conv_b = (const float*)d_in[4];
    const float* W_out  = (const float*)d_in[5];
    const float* b_out  = (const float*)d_in[6];
    float* out = (float*)d_out;

    __half *x16, *h16, *y16, *wi, *wo, *w2;
    cudaGetSymbolAddress((void**)&x16, g_x16);
    cudaGetSymbolAddress((void**)&h16, g_h16);
    cudaGetSymbolAddress((void**)&y16, g_y16);
    cudaGetSymbolAddress((void**)&wi,  g_wi);
    cudaGetSymbolAddress((void**)&wo,  g_wo);
    cudaGetSymbolAddress((void**)&w2,  g_w2);

    cudaFuncSetAttribute((gemm_p<false, false, false, 2048, 32, 4096, 0>),
                         cudaFuncAttributeMaxDynamicSharedMemorySize, SMEM_TOTAL);
    cudaFuncSetAttribute((gemm_p<true, true, false, 2048, 32, 4096, 1>),
                         cudaFuncAttributeMaxDynamicSharedMemorySize, SMEM_TOTAL);
    cudaFuncSetAttribute((gemm_p<false, false, true, 4096, 16, 2048, 2>),
                         cudaFuncAttributeMaxDynamicSharedMemorySize, SMEM_TOTAL);

    prep_all_kernel<<<(P3 + 255) / 256, 256>>>(x, W_in, W_out, conv_w,
                                               x16, wi, wo, w2);

    // Stage 1: h = x @ W_in^T + b_in               (K=2048, N=4096) -> fp16
    gemm_p<false, false, false, 2048, 32, 4096, 0><<<NCTA, NTHR, SMEM_TOTAL>>>(
        x16, wi, b_in, h16);
    // Stage 2: y = silu(im2col(h) @ w2^T + conv_b) (K=2048, N=4096) -> fp16
    gemm_p<true, true, false, 2048, 32, 4096, 1><<<NCTA, NTHR, SMEM_TOTAL>>>(
        h16, w2, conv_b, y16);
    // Stage 3: out = y @ W_out^T + b_out           (K=4096, N=2048) -> fp32
    gemm_p<false, false, true, 4096, 16, 2048, 2><<<NCTA, NTHR, SMEM_TOTAL>>>(
        y16, wo, b_out, out);
}